// round 4
// baseline (speedup 1.0000x reference)
#include <cuda_runtime.h>
#include <cuda_fp16.h>
#include <math.h>

#define NMAX 100000
#define C    64
#define HID  16
#define KNN  16
#define FULL 0xFFFFFFFFu

// Scratch (device globals: no allocation allowed in kernel_launch)
__device__ float g_outse[(size_t)NMAX * C];   // stage-1 output (gated features)
__device__ float g_rowstat[(size_t)NMAX * 2]; // per-point (rowsum, rowmax) of outse
__device__ float g_z[(size_t)NMAX * 2];       // stage-2 (mean, max) pooled stats
__device__ __align__(16) __half2 g_xh2[(size_t)NMAX * C / 2]; // fp16 mirror of x_F

// ---------------------------------------------------------------------------
// Kernel 0: fp16 mirror of x_F. One streaming pass; halves all gather bytes.
//   Thread handles 8 floats -> 4 half2 (one 16B store).
// ---------------------------------------------------------------------------
__global__ __launch_bounds__(256) void k0_tohalf(const float* __restrict__ xF, int n8)
{
    int i = blockIdx.x * blockDim.x + threadIdx.x;
    if (i >= n8) return;
    const float4* src = (const float4*)xF;
    float4 a = __ldg(src + 2 * i);
    float4 b = __ldg(src + 2 * i + 1);
    __half2 h0 = __floats2half2_rn(a.x, a.y);
    __half2 h1 = __floats2half2_rn(a.z, a.w);
    __half2 h2 = __floats2half2_rn(b.x, b.y);
    __half2 h3 = __floats2half2_rn(b.z, b.w);
    uint4 packed = make_uint4(*(unsigned*)&h0, *(unsigned*)&h1,
                              *(unsigned*)&h2, *(unsigned*)&h3);
    ((uint4*)g_xh2)[i] = packed;
}

// ---------------------------------------------------------------------------
// Kernel 1: channel attention. HALF-WARP per point (2 points per warp).
//   Lane layout: half = lane>>4, hl = lane&15. Point n = 2*warp + half.
//   Lane hl owns channels 4hl..4hl+3. Gather reads the fp16 mirror
//   (row = 128B = ONE cache line); accumulation in fp32.
// ---------------------------------------------------------------------------
__global__ __launch_bounds__(256) void k1_gate(
    const float* __restrict__ xF,
    const float* __restrict__ W1,   // (C, HID)
    const float* __restrict__ b1,   // (HID,)
    const float* __restrict__ W2,   // (HID, C)
    const float* __restrict__ b2,   // (C,)
    const int*   __restrict__ idx,  // (N, KNN)
    int N)
{
    // sW1p[j*16+hl] = (W1[4hl+0][j], ..., W1[4hl+3][j])
    // sW2p[j*16+hl] = (W2[j][4hl+0], ..., W2[j][4hl+3])
    __shared__ float4 sW1p[HID * 16];
    __shared__ float4 sW2p[HID * 16];

    const int tid = threadIdx.x;
    for (int i = tid; i < HID * 16; i += blockDim.x) {
        int j = i >> 4, h = i & 15;
        sW1p[i] = make_float4(W1[(4*h+0)*HID + j], W1[(4*h+1)*HID + j],
                              W1[(4*h+2)*HID + j], W1[(4*h+3)*HID + j]);
        sW2p[i] = __ldg((const float4*)W2 + i);
    }
    __syncthreads();

    const int lane = tid & 31;
    const int half = lane >> 4;
    const int hl   = lane & 15;
    const int warp = blockIdx.x * (blockDim.x >> 5) + (tid >> 5);
    const int n    = 2 * warp + half;
    if (n >= N) return;

    const float  b1v = __ldg(b1 + hl);
    const float4 b2v = __ldg((const float4*)(b2 + 4 * hl));

    // ---- neighbor indices: 4 uniform-per-half LDG.128 ----
    const int4* ib = (const int4*)(idx + (size_t)n * KNN);
    int4 q0 = __ldg(ib + 0), q1 = __ldg(ib + 1),
         q2 = __ldg(ib + 2), q3 = __ldg(ib + 3);
    const int nb[KNN] = { q0.x, q0.y, q0.z, q0.w,  q1.x, q1.y, q1.z, q1.w,
                          q2.x, q2.y, q2.z, q2.w,  q3.x, q3.y, q3.z, q3.w };

    // ---- gather + pool: 16 fp16 rows x 128B (one line each), fp32 accum ----
    float4 m  = make_float4(0.f, 0.f, 0.f, 0.f);
    float4 mx = make_float4(-INFINITY, -INFINITY, -INFINITY, -INFINITY);
    #pragma unroll
    for (int k = 0; k < KNN; k++) {
        uint2 raw = __ldg((const uint2*)(g_xh2 + (size_t)nb[k] * (C/2) + 2 * hl));
        float2 f0 = __half22float2(*(__half2*)&raw.x);
        float2 f1 = __half22float2(*(__half2*)&raw.y);
        m.x += f0.x; m.y += f0.y; m.z += f1.x; m.w += f1.y;
        mx.x = fmaxf(mx.x, f0.x); mx.y = fmaxf(mx.y, f0.y);
        mx.z = fmaxf(mx.z, f1.x); mx.w = fmaxf(mx.w, f1.y);
    }
    const float inv = 1.f / KNN;
    m.x *= inv; m.y *= inv; m.z *= inv; m.w *= inv;

    // ---- layer-1 partials: p[2j]=mean-path unit j, p[2j+1]=max-path unit j ----
    float p[32];
    #pragma unroll
    for (int j = 0; j < HID; j++) {
        float4 w = sW1p[j * 16 + hl];
        p[2*j]   = m.x*w.x  + m.y*w.y  + m.z*w.z  + m.w*w.w;
        p[2*j+1] = mx.x*w.x + mx.y*w.y + mx.z*w.z + mx.w*w.w;
    }

    // ---- 16-lane vector-halving butterfly: 4 steps, 30 shfls for 32 values.
    //      Final: lane hl holds p[0]=mean_hl, p[1]=max_hl. ----
    #pragma unroll
    for (int step = 0; step < 4; step++) {
        const int  off = 8 >> step;     // 8,4,2,1 (stays within half)
        const int  nv  = 16 >> step;    // 16,8,4,2
        const bool up  = (hl & off) != 0;
        #pragma unroll
        for (int i = 0; i < nv; i++) {
            float send = up ? p[i] : p[i + nv];
            float recv = __shfl_xor_sync(FULL, send, off);
            float keep = up ? p[i + nv] : p[i];
            p[i] = keep + recv;
        }
    }

    // hs[hl] = relu(mean_hl + b1) + relu(max_hl + b1), in-lane
    float hs = fmaxf(p[0] + b1v, 0.f) + fmaxf(p[1] + b1v, 0.f);

    // ---- layer 2: a[c] = 2*b2[c] + sum_j hs[j]*W2[j][c] ----
    float4 a = make_float4(2.f*b2v.x, 2.f*b2v.y, 2.f*b2v.z, 2.f*b2v.w);
    #pragma unroll
    for (int j = 0; j < HID; j++) {
        float  hj = __shfl_sync(FULL, hs, (lane & 16) | j);
        float4 w  = sW2p[j * 16 + hl];
        a.x += hj*w.x; a.y += hj*w.y; a.z += hj*w.z; a.w += hj*w.w;
    }

    float4 xv = __ldg((const float4*)(xF + (size_t)n * C + 4 * hl));
    float4 o;
    o.x = xv.x / (1.f + __expf(-a.x));
    o.y = xv.y / (1.f + __expf(-a.y));
    o.z = xv.z / (1.f + __expf(-a.z));
    o.w = xv.w / (1.f + __expf(-a.w));
    *(float4*)(g_outse + (size_t)n * C + 4 * hl) = o;

    // ---- rowsum/rowmax of outse (16-lane reduction per half) ----
    float s  = o.x + o.y + o.z + o.w;
    float mm = fmaxf(fmaxf(o.x, o.y), fmaxf(o.z, o.w));
    #pragma unroll
    for (int off = 8; off >= 1; off >>= 1) {
        s  += __shfl_xor_sync(FULL, s, off);
        mm  = fmaxf(mm, __shfl_xor_sync(FULL, mm, off));
    }
    if (hl == 0)
        *(float2*)(g_rowstat + 2 * (size_t)n) = make_float2(s, mm);
}

// ---------------------------------------------------------------------------
// Kernel 2: z = (mean over k*c, max over k*c) of outse[idx], factored through
//           per-point rowstats. thread-per-point, 16 x 8B gathers.
// ---------------------------------------------------------------------------
__global__ __launch_bounds__(256) void k2_z(const int* __restrict__ idx, int N)
{
    int n = blockIdx.x * blockDim.x + threadIdx.x;
    if (n >= N) return;
    const int4* ib = (const int4*)(idx + (size_t)n * KNN);
    int4 q0 = __ldg(ib + 0), q1 = __ldg(ib + 1),
         q2 = __ldg(ib + 2), q3 = __ldg(ib + 3);
    const int nb[KNN] = { q0.x, q0.y, q0.z, q0.w,  q1.x, q1.y, q1.z, q1.w,
                          q2.x, q2.y, q2.z, q2.w,  q3.x, q3.y, q3.z, q3.w };
    float s = 0.f, mx = -INFINITY;
    #pragma unroll
    for (int k = 0; k < KNN; k++) {
        float2 rs = __ldg((const float2*)(g_rowstat + 2 * (size_t)nb[k]));
        s += rs.x;
        mx = fmaxf(mx, rs.y);
    }
    *(float2*)(g_z + 2 * (size_t)n) = make_float2(s * (1.f / (KNN * C)), mx);
}

// ---------------------------------------------------------------------------
// Kernel 3: sparse conv3d(2->1) over 27 voxel neighbors + final gating.
//           warp-per-point: lanes 0..26 each handle one conv tap.
// ---------------------------------------------------------------------------
__global__ __launch_bounds__(256) void k3_out(
    const float* __restrict__ conv_w,   // (27, 2, 1)
    const int*   __restrict__ conv_idx, // (N, 27)
    float*       __restrict__ out,
    int N)
{
    const int n    = (blockIdx.x * blockDim.x + threadIdx.x) >> 5;
    const int lane = threadIdx.x & 31;
    if (n >= N) return;

    float f = 0.f;
    if (lane < 27) {
        int m = __ldg(conv_idx + (size_t)n * 27 + lane);
        if (m >= 0) {
            float2 zz = __ldg((const float2*)(g_z + 2 * (size_t)m));
            float2 cw = __ldg((const float2*)(conv_w + 2 * lane));
            f = zz.x * cw.x + zz.y * cw.y;
        }
    }
    #pragma unroll
    for (int off = 16; off >= 1; off >>= 1)
        f += __shfl_xor_sync(FULL, f, off);

    float sg = 1.f / (1.f + __expf(-f));
    float2 o = *(const float2*)(g_outse + (size_t)n * C + 2 * lane);
    *(float2*)(out + (size_t)n * C + 2 * lane) = make_float2(o.x * sg, o.y * sg);
}

// ---------------------------------------------------------------------------
// Launch: inputs in metadata order:
//   0 x_F (N*C f32), 1 W1 (C*HID), 2 b1 (HID), 3 W2 (HID*C), 4 b2 (C),
//   5 conv_w (27*2), 6 idx (N*KNN i32), 7 conv_idx (N*27 i32)
// ---------------------------------------------------------------------------
extern "C" void kernel_launch(void* const* d_in, const int* in_sizes, int n_in,
                              void* d_out, int out_size)
{
    const float* xF  = (const float*)d_in[0];
    const float* W1  = (const float*)d_in[1];
    const float* b1  = (const float*)d_in[2];
    const float* W2  = (const float*)d_in[3];
    const float* b2  = (const float*)d_in[4];
    const float* cw  = (const float*)d_in[5];
    const int*   idx = (const int*)d_in[6];
    const int*   cid = (const int*)d_in[7];
    float*       out = (float*)d_out;

    const int N  = in_sizes[0] / C;                // 100000
    const int n8 = (N * C) / 8;                    // fp32->fp16 pack units

    k0_tohalf<<<(n8 + 255) / 256, 256>>>(xF, n8);

    const int npairs    = (N + 1) / 2;             // 2 points per warp
    const int k1_blocks = (npairs + 7) / 8;        // 8 warps per block
    k1_gate<<<k1_blocks, 256>>>(xF, W1, b1, W2, b2, idx, N);
    k2_z  <<<(N + 255) / 256, 256>>>(idx, N);
    k3_out<<<(N * 32 + 255) / 256, 256>>>(cw, cid, out, N);
}

// round 5
// speedup vs baseline: 1.1932x; 1.1932x over previous
#include <cuda_runtime.h>
#include <cuda_fp16.h>
#include <math.h>

#define NMAX 100000
#define C    64
#define HID  16
#define KNN  16
#define FULL 0xFFFFFFFFu

// Scratch (device globals)
__device__ float g_outse[(size_t)NMAX * C];
__device__ float g_rowstat[(size_t)NMAX * 2];
__device__ float g_z[(size_t)NMAX * 2];
__device__ float g_gate[(size_t)NMAX];
__device__ __align__(16) __half2 g_xh2[(size_t)NMAX * C / 2]; // fp16 mirror of x_F

// ---------------------------------------------------------------------------
// Kernel 0: fp16 mirror of x_F (row = 128B = one cache line).
// ---------------------------------------------------------------------------
__global__ __launch_bounds__(256) void k0_tohalf(const float* __restrict__ xF, int n8)
{
    int i = blockIdx.x * blockDim.x + threadIdx.x;
    if (i >= n8) return;
    const float4* src = (const float4*)xF;
    float4 a = __ldg(src + 2 * i);
    float4 b = __ldg(src + 2 * i + 1);
    __half2 h0 = __floats2half2_rn(a.x, a.y);
    __half2 h1 = __floats2half2_rn(a.z, a.w);
    __half2 h2 = __floats2half2_rn(b.x, b.y);
    __half2 h3 = __floats2half2_rn(b.z, b.w);
    ((uint4*)g_xh2)[i] = make_uint4(*(unsigned*)&h0, *(unsigned*)&h1,
                                    *(unsigned*)&h2, *(unsigned*)&h3);
}

// ---------------------------------------------------------------------------
// Kernel 1: channel attention. QUARTER-WARP per point (4 points per warp).
//   q = lane>>3, ql = lane&7. Point n = 4*warp + q. Lane owns channels
//   8ql..8ql+7. Gather: one uint4 (8 fp16) per lane -> 128B row = 1 line.
// ---------------------------------------------------------------------------
__global__ __launch_bounds__(256) void k1_gate(
    const float* __restrict__ xF,
    const float* __restrict__ W1,   // (C, HID)
    const float* __restrict__ b1,   // (HID,)
    const float* __restrict__ W2,   // (HID, C)
    const float* __restrict__ b2,   // (C,)
    const int*   __restrict__ idx,  // (N, KNN)
    int N)
{
    // sW1a[j*8+ql] = W1[8ql+0..3][j], sW1b = W1[8ql+4..7][j]
    // sW2a[j*8+ql] = W2[j][8ql+0..3], sW2b = W2[j][8ql+4..7]
    __shared__ float4 sW1a[HID * 8], sW1b[HID * 8];
    __shared__ float4 sW2a[HID * 8], sW2b[HID * 8];

    const int tid = threadIdx.x;
    for (int i = tid; i < HID * 8; i += blockDim.x) {
        int j = i >> 3, h = i & 7;
        sW1a[i] = make_float4(W1[(8*h+0)*HID + j], W1[(8*h+1)*HID + j],
                              W1[(8*h+2)*HID + j], W1[(8*h+3)*HID + j]);
        sW1b[i] = make_float4(W1[(8*h+4)*HID + j], W1[(8*h+5)*HID + j],
                              W1[(8*h+6)*HID + j], W1[(8*h+7)*HID + j]);
        sW2a[i] = __ldg((const float4*)W2 + j * 16 + 2 * h);
        sW2b[i] = __ldg((const float4*)W2 + j * 16 + 2 * h + 1);
    }
    __syncthreads();

    const int lane  = tid & 31;
    const int q     = lane >> 3;
    const int ql    = lane & 7;
    const int qbase = lane & 24;
    const int warp  = blockIdx.x * (blockDim.x >> 5) + (tid >> 5);
    if (4 * warp >= N) return;
    int n = 4 * warp + q;
    if (n >= N) n = N - 1;          // duplicate work, deterministic (N%4==0 anyway)

    const float2 b1v = __ldg((const float2*)b1 + ql);
    const float4 b2a = __ldg((const float4*)b2 + 2 * ql);
    const float4 b2b = __ldg((const float4*)b2 + 2 * ql + 1);

    // ---- neighbor indices: 4 quarter-uniform LDG.128 ----
    const int4* ib = (const int4*)(idx + (size_t)n * KNN);
    int4 i0 = __ldg(ib + 0), i1 = __ldg(ib + 1),
         i2 = __ldg(ib + 2), i3 = __ldg(ib + 3);
    const int nb[KNN] = { i0.x, i0.y, i0.z, i0.w,  i1.x, i1.y, i1.z, i1.w,
                          i2.x, i2.y, i2.z, i2.w,  i3.x, i3.y, i3.z, i3.w };

    // ---- gather + pool: 16 rows, 1 uint4 per lane (fp16), fp32 accum ----
    float m[8]  = {0.f, 0.f, 0.f, 0.f, 0.f, 0.f, 0.f, 0.f};
    float mx[8] = {-INFINITY, -INFINITY, -INFINITY, -INFINITY,
                   -INFINITY, -INFINITY, -INFINITY, -INFINITY};
    #pragma unroll
    for (int k = 0; k < KNN; k++) {
        uint4 raw = __ldg((const uint4*)(g_xh2 + (size_t)nb[k] * (C/2)) + ql);
        float2 f0 = __half22float2(*(__half2*)&raw.x);
        float2 f1 = __half22float2(*(__half2*)&raw.y);
        float2 f2 = __half22float2(*(__half2*)&raw.z);
        float2 f3 = __half22float2(*(__half2*)&raw.w);
        m[0] += f0.x; m[1] += f0.y; m[2] += f1.x; m[3] += f1.y;
        m[4] += f2.x; m[5] += f2.y; m[6] += f3.x; m[7] += f3.y;
        mx[0] = fmaxf(mx[0], f0.x); mx[1] = fmaxf(mx[1], f0.y);
        mx[2] = fmaxf(mx[2], f1.x); mx[3] = fmaxf(mx[3], f1.y);
        mx[4] = fmaxf(mx[4], f2.x); mx[5] = fmaxf(mx[5], f2.y);
        mx[6] = fmaxf(mx[6], f3.x); mx[7] = fmaxf(mx[7], f3.y);
    }
    const float inv = 1.f / KNN;
    #pragma unroll
    for (int i = 0; i < 8; i++) m[i] *= inv;

    // ---- mean-path layer-1 partials + 8-lane butterfly (14 shfls) ----
    float pm[HID];
    #pragma unroll
    for (int j = 0; j < HID; j++) {
        float4 wa = sW1a[j * 8 + ql], wb = sW1b[j * 8 + ql];
        pm[j] = m[0]*wa.x + m[1]*wa.y + m[2]*wa.z + m[3]*wa.w
              + m[4]*wb.x + m[5]*wb.y + m[6]*wb.z + m[7]*wb.w;
    }
    #pragma unroll
    for (int step = 0; step < 3; step++) {
        const int  off = 4 >> step;   // 4,2,1 (stays within quarter)
        const int  nv  = 8 >> step;   // 8,4,2
        const bool up  = (ql & off) != 0;
        #pragma unroll
        for (int i = 0; i < nv; i++) {
            float send = up ? pm[i] : pm[i + nv];
            float recv = __shfl_xor_sync(FULL, send, off);
            float keep = up ? pm[i + nv] : pm[i];
            pm[i] = keep + recv;
        }
    }
    const float rm0 = pm[0], rm1 = pm[1];  // mean dot for hidden 2ql, 2ql+1

    // ---- max-path layer-1 partials + butterfly ----
    float px[HID];
    #pragma unroll
    for (int j = 0; j < HID; j++) {
        float4 wa = sW1a[j * 8 + ql], wb = sW1b[j * 8 + ql];
        px[j] = mx[0]*wa.x + mx[1]*wa.y + mx[2]*wa.z + mx[3]*wa.w
              + mx[4]*wb.x + mx[5]*wb.y + mx[6]*wb.z + mx[7]*wb.w;
    }
    #pragma unroll
    for (int step = 0; step < 3; step++) {
        const int  off = 4 >> step;
        const int  nv  = 8 >> step;
        const bool up  = (ql & off) != 0;
        #pragma unroll
        for (int i = 0; i < nv; i++) {
            float send = up ? px[i] : px[i + nv];
            float recv = __shfl_xor_sync(FULL, send, off);
            float keep = up ? px[i + nv] : px[i];
            px[i] = keep + recv;
        }
    }

    // hidden activations for units 2ql (hs0) and 2ql+1 (hs1), in-lane
    float hs0 = fmaxf(rm0 + b1v.x, 0.f) + fmaxf(px[0] + b1v.x, 0.f);
    float hs1 = fmaxf(rm1 + b1v.y, 0.f) + fmaxf(px[1] + b1v.y, 0.f);

    // ---- layer 2: a[c] = 2*b2[c] + sum_j hs[j]*W2[j][c] ----
    float4 a0 = make_float4(2.f*b2a.x, 2.f*b2a.y, 2.f*b2a.z, 2.f*b2a.w);
    float4 a1 = make_float4(2.f*b2b.x, 2.f*b2b.y, 2.f*b2b.z, 2.f*b2b.w);
    #pragma unroll
    for (int jj = 0; jj < 8; jj++) {
        float h0 = __shfl_sync(FULL, hs0, qbase | jj);   // hidden j = 2jj
        float h1 = __shfl_sync(FULL, hs1, qbase | jj);   // hidden j = 2jj+1
        float4 wa = sW2a[(2*jj) * 8 + ql],   wb = sW2b[(2*jj) * 8 + ql];
        a0.x += h0*wa.x; a0.y += h0*wa.y; a0.z += h0*wa.z; a0.w += h0*wa.w;
        a1.x += h0*wb.x; a1.y += h0*wb.y; a1.z += h0*wb.z; a1.w += h0*wb.w;
        float4 wc = sW2a[(2*jj+1) * 8 + ql], wd = sW2b[(2*jj+1) * 8 + ql];
        a0.x += h1*wc.x; a0.y += h1*wc.y; a0.z += h1*wc.z; a0.w += h1*wc.w;
        a1.x += h1*wd.x; a1.y += h1*wd.y; a1.z += h1*wd.z; a1.w += h1*wd.w;
    }

    float4 xv0 = __ldg((const float4*)(xF + (size_t)n * C) + 2 * ql);
    float4 xv1 = __ldg((const float4*)(xF + (size_t)n * C) + 2 * ql + 1);
    float4 o0, o1;
    o0.x = xv0.x / (1.f + __expf(-a0.x));
    o0.y = xv0.y / (1.f + __expf(-a0.y));
    o0.z = xv0.z / (1.f + __expf(-a0.z));
    o0.w = xv0.w / (1.f + __expf(-a0.w));
    o1.x = xv1.x / (1.f + __expf(-a1.x));
    o1.y = xv1.y / (1.f + __expf(-a1.y));
    o1.z = xv1.z / (1.f + __expf(-a1.z));
    o1.w = xv1.w / (1.f + __expf(-a1.w));
    ((float4*)(g_outse + (size_t)n * C))[2 * ql]     = o0;
    ((float4*)(g_outse + (size_t)n * C))[2 * ql + 1] = o1;

    // ---- rowsum/rowmax over the quarter ----
    float s  = (o0.x + o0.y + o0.z + o0.w) + (o1.x + o1.y + o1.z + o1.w);
    float mm = fmaxf(fmaxf(fmaxf(o0.x, o0.y), fmaxf(o0.z, o0.w)),
                     fmaxf(fmaxf(o1.x, o1.y), fmaxf(o1.z, o1.w)));
    #pragma unroll
    for (int off = 4; off >= 1; off >>= 1) {
        s  += __shfl_xor_sync(FULL, s, off);
        mm  = fmaxf(mm, __shfl_xor_sync(FULL, mm, off));
    }
    if (ql == 0)
        *(float2*)(g_rowstat + 2 * (size_t)n) = make_float2(s, mm);
}

// ---------------------------------------------------------------------------
// Kernel 2: z = (mean, max) pooled over neighbors, via per-point rowstats.
// ---------------------------------------------------------------------------
__global__ __launch_bounds__(256) void k2_z(const int* __restrict__ idx, int N)
{
    int n = blockIdx.x * blockDim.x + threadIdx.x;
    if (n >= N) return;
    const int4* ib = (const int4*)(idx + (size_t)n * KNN);
    int4 q0 = __ldg(ib + 0), q1 = __ldg(ib + 1),
         q2 = __ldg(ib + 2), q3 = __ldg(ib + 3);
    const int nb[KNN] = { q0.x, q0.y, q0.z, q0.w,  q1.x, q1.y, q1.z, q1.w,
                          q2.x, q2.y, q2.z, q2.w,  q3.x, q3.y, q3.z, q3.w };
    float s = 0.f, mx = -INFINITY;
    #pragma unroll
    for (int k = 0; k < KNN; k++) {
        float2 rs = __ldg((const float2*)(g_rowstat + 2 * (size_t)nb[k]));
        s += rs.x;
        mx = fmaxf(mx, rs.y);
    }
    *(float2*)(g_z + 2 * (size_t)n) = make_float2(s * (1.f / (KNN * C)), mx);
}

// ---------------------------------------------------------------------------
// Kernel 3a: sparse conv gate. THREAD-per-point: 27 independent gathers (MLP=27).
// ---------------------------------------------------------------------------
__global__ __launch_bounds__(256) void k3a_gate(
    const float* __restrict__ conv_w,   // (27, 2)
    const int*   __restrict__ conv_idx, // (N, 27)
    int N)
{
    int n = blockIdx.x * blockDim.x + threadIdx.x;
    if (n >= N) return;
    const int* cb = conv_idx + (size_t)n * 27;
    float f = 0.f;
    #pragma unroll
    for (int k = 0; k < 27; k++) {
        int m = __ldg(cb + k);
        if (m >= 0) {
            float2 zz = __ldg((const float2*)g_z + m);
            float2 cw = __ldg((const float2*)conv_w + k);
            f += zz.x * cw.x + zz.y * cw.y;
        }
    }
    g_gate[n] = 1.f / (1.f + __expf(-f));
}

// ---------------------------------------------------------------------------
// Kernel 3b: pure streaming multiply out = outse * gate (2 float4 per thread).
// ---------------------------------------------------------------------------
__global__ __launch_bounds__(256) void k3b_mul(float* __restrict__ out, int N)
{
    int t = blockIdx.x * blockDim.x + threadIdx.x;
    if (t >= N * 8) return;
    int n   = t >> 3;
    int seg = t & 7;
    float g = __ldg(g_gate + n);
    const float4* src = (const float4*)(g_outse + (size_t)n * C) + 2 * seg;
    float4 a = src[0], b = src[1];
    float4* dst = (float4*)(out + (size_t)n * C) + 2 * seg;
    dst[0] = make_float4(a.x * g, a.y * g, a.z * g, a.w * g);
    dst[1] = make_float4(b.x * g, b.y * g, b.z * g, b.w * g);
}

// ---------------------------------------------------------------------------
// Launch
// ---------------------------------------------------------------------------
extern "C" void kernel_launch(void* const* d_in, const int* in_sizes, int n_in,
                              void* d_out, int out_size)
{
    const float* xF  = (const float*)d_in[0];
    const float* W1  = (const float*)d_in[1];
    const float* b1  = (const float*)d_in[2];
    const float* W2  = (const float*)d_in[3];
    const float* b2  = (const float*)d_in[4];
    const float* cw  = (const float*)d_in[5];
    const int*   idx = (const int*)d_in[6];
    const int*   cid = (const int*)d_in[7];
    float*       out = (float*)d_out;

    const int N  = in_sizes[0] / C;                // 100000
    const int n8 = (N * C) / 8;

    k0_tohalf<<<(n8 + 255) / 256, 256>>>(xF, n8);

    const int nquads    = (N + 3) / 4;             // 4 points per warp
    const int k1_blocks = (nquads + 7) / 8;        // 8 warps per block
    k1_gate<<<k1_blocks, 256>>>(xF, W1, b1, W2, b2, idx, N);
    k2_z    <<<(N + 255) / 256, 256>>>(idx, N);
    k3a_gate<<<(N + 255) / 256, 256>>>(cw, cid, N);
    k3b_mul <<<(N * 8 + 255) / 256, 256>>>(out, N);
}